// round 14
// baseline (speedup 1.0000x reference)
#include <cuda_runtime.h>

#define NB 32
#define NCH 3
#define THREADS 128
#define B_PER_CHUNK 32
#define CHUNK_ELEMS (512*512)
#define CHUNK_F4   (CHUNK_ELEMS/4)         // 65536 float4 per (n,c) chunk
#define NCHUNKS    (16*3)                  // 48
#define NBLOCKS    (NCHUNKS * B_PER_CHUNK) // 1536 work blocks
#define STRIDE     (B_PER_CHUNK * THREADS) // 4096
#define NSLOTS 32                          // contention spreading for fp64 atomics

// Slot-spread accumulators: per-address chain depth ~16 -> fast end-of-kernel
// drain -> blocks retire promptly. Zero-initialized at module load;
// final_kernel resets after reading (graph-replay determinism).
__device__ double g_sum_d[NSLOTS][NCH * NB];
__device__ double g_cnt [NSLOTS][NCH * NB];

__device__ __forceinline__ void accum(float2* h, float xc, float pc, float tc, int tid)
{
    int b = (int)(xc * 32.0f);        // inputs uniform [0,1)
    b = min(b, NB - 1);               // x slightly <1 can round x*32 up to 32.0
    float2* e = &h[b * THREADS + tid];
    float2 v = *e;                    // LDS.64, conflict-free (lane stride 8B)
    v.x += pc - tc;
    v.y += 1.0f;
    *e = v;                           // STS.64
}

__global__ __launch_bounds__(THREADS, 7)
void hist_kernel(const float4* __restrict__ pred,
                 const float4* __restrict__ targ,
                 const float4* __restrict__ x)
{
    // Per-thread privatized {sum(p-t), count} histogram: h[bin*128 + tid].
    __shared__ float2 h[NB * THREADS];

    const int tid = threadIdx.x;

    #pragma unroll
    for (int b = 0; b < NB; b++)
        h[b * THREADS + tid] = make_float2(0.0f, 0.0f);
    __syncthreads();

    const int chunk = blockIdx.x / B_PER_CHUNK;   // (n*3 + c)
    const int sub   = blockIdx.x % B_PER_CHUNK;
    const int chan  = chunk % NCH;
    const int slot  = blockIdx.x & (NSLOTS - 1);
    const size_t base = (size_t)chunk * CHUNK_F4;

    int i = sub * THREADS + tid;
    #pragma unroll 2
    for (int k = 0; k < CHUNK_F4 / (2 * STRIDE); k++, i += 2 * STRIDE) {
        float4 xa = __ldcs(&x   [base + i]);
        float4 pa = __ldcs(&pred[base + i]);
        float4 ta = __ldcs(&targ[base + i]);
        float4 xb = __ldcs(&x   [base + i + STRIDE]);
        float4 pb = __ldcs(&pred[base + i + STRIDE]);
        float4 tb = __ldcs(&targ[base + i + STRIDE]);

        accum(h, xa.x, pa.x, ta.x, tid);
        accum(h, xa.y, pa.y, ta.y, tid);
        accum(h, xa.z, pa.z, ta.z, tid);
        accum(h, xa.w, pa.w, ta.w, tid);

        accum(h, xb.x, pb.x, tb.x, tid);
        accum(h, xb.y, pb.y, tb.y, tid);
        accum(h, xb.z, pb.z, tb.z, tid);
        accum(h, xb.w, pb.w, tb.w, tid);
    }
    __syncthreads();

    // Block reduce: 128 threads = 32 bins x 4 quarters of 32 entries.
    const int bin = tid >> 2;
    const int j   = tid & 3;
    const int bi  = bin * THREADS + j * 32;

    float vd = 0.0f, vc = 0.0f;
    #pragma unroll
    for (int k = 0; k < 32; k++) {
        int kk = (k + tid) & 31;
        float2 e = h[bi + kk];
        vd += e.x;
        vc += e.y;
    }

    vd += __shfl_down_sync(0xffffffffu, vd, 1);
    vc += __shfl_down_sync(0xffffffffu, vc, 1);
    vd += __shfl_down_sync(0xffffffffu, vd, 2);
    vc += __shfl_down_sync(0xffffffffu, vc, 2);

    if (j == 0) {
        int g = chan * NB + bin;
        atomicAdd(&g_sum_d[slot][g], (double)vd);
        atomicAdd(&g_cnt [slot][g], (double)vc);
    }
}

// 768 threads: tid = entry*8 + sg; each thread sums slots {sg, sg+8, sg+16, sg+24}.
__global__ void final_kernel(float* __restrict__ out) {
    const int tid   = threadIdx.x;
    const int entry = tid >> 3;      // 0..95
    const int sg    = tid & 7;

    double sdv = 0.0, cnt = 0.0;
    #pragma unroll
    for (int s = sg; s < NSLOTS; s += 8) {
        sdv += g_sum_d[s][entry];
        cnt += g_cnt [s][entry];
        g_sum_d[s][entry] = 0.0;     // reset for next launch
        g_cnt [s][entry] = 0.0;
    }
    // reduce over the 8-lane subgroup (contiguous lanes within a warp)
    #pragma unroll
    for (int o = 4; o > 0; o >>= 1) {
        sdv += __shfl_down_sync(0xffffffffu, sdv, o);
        cnt += __shfl_down_sync(0xffffffffu, cnt, o);
    }

    __shared__ float buf[96];
    if (sg == 0)
        buf[entry] = (cnt > 0.0) ? (float)fabs(sdv / cnt) : 0.0f;
    __syncthreads();

    if (tid < 32) {
        float v = buf[tid] + buf[tid + 32] + buf[tid + 64];
        #pragma unroll
        for (int o = 16; o > 0; o >>= 1)
            v += __shfl_down_sync(0xffffffffu, v, o);
        if (tid == 0) out[0] = v / 96.0f;
    }
}

extern "C" void kernel_launch(void* const* d_in, const int* in_sizes, int n_in,
                              void* d_out, int out_size)
{
    const float4* pred = (const float4*)d_in[0];
    const float4* targ = (const float4*)d_in[1];
    const float4* x    = (const float4*)d_in[2];
    float* out = (float*)d_out;

    hist_kernel<<<NBLOCKS, THREADS>>>(pred, targ, x);
    final_kernel<<<1, 768>>>(out);
}

// round 15
// speedup vs baseline: 1.2382x; 1.2382x over previous
#include <cuda_runtime.h>

#define NB 32
#define NCH 3
#define THREADS 128
#define B_PER_CHUNK 32
#define CHUNK_ELEMS (512*512)
#define CHUNK_F4   (CHUNK_ELEMS/4)         // 65536 float4 per (n,c) chunk
#define NCHUNKS    (16*3)                  // 48
#define NBLOCKS    (NCHUNKS * B_PER_CHUNK) // 1536 small blocks -> HW load balance
#define STRIDE     (B_PER_CHUNK * THREADS) // 4096

// Global accumulators. Zero-initialized at module load; final_kernel resets
// them after reading, so every (graph-replayed) launch starts from zero.
__device__ double g_sum_d[NCH * NB];
__device__ double g_cnt [NCH * NB];

__device__ __forceinline__ void accum(float2* h, float xc, float pc, float tc, int tid)
{
    int b = (int)(xc * 32.0f);        // inputs uniform [0,1)
    b = min(b, NB - 1);               // x slightly <1 can round x*32 up to 32.0
    float2* e = &h[b * THREADS + tid];
    float2 v = *e;                    // LDS.64, conflict-free (lane stride 8B)
    v.x += pc - tc;
    v.y += 1.0f;
    *e = v;                           // STS.64
}

__global__ __launch_bounds__(THREADS, 7)
void hist_kernel(const float4* __restrict__ pred,
                 const float4* __restrict__ targ,
                 const float4* __restrict__ x)
{
    // Per-thread privatized {sum(p-t), count} histogram: h[bin*128 + tid].
    __shared__ float2 h[NB * THREADS];

    const int tid = threadIdx.x;

    #pragma unroll
    for (int b = 0; b < NB; b++)
        h[b * THREADS + tid] = make_float2(0.0f, 0.0f);
    __syncthreads();

    const int chunk = blockIdx.x / B_PER_CHUNK;   // (n*3 + c)
    const int sub   = blockIdx.x % B_PER_CHUNK;
    const int chan  = chunk % NCH;
    const size_t base = (size_t)chunk * CHUNK_F4;

    int i = sub * THREADS + tid;
    #pragma unroll 2
    for (int k = 0; k < CHUNK_F4 / (2 * STRIDE); k++, i += 2 * STRIDE) {
        float4 xa = __ldcs(&x   [base + i]);
        float4 pa = __ldcs(&pred[base + i]);
        float4 ta = __ldcs(&targ[base + i]);
        float4 xb = __ldcs(&x   [base + i + STRIDE]);
        float4 pb = __ldcs(&pred[base + i + STRIDE]);
        float4 tb = __ldcs(&targ[base + i + STRIDE]);

        accum(h, xa.x, pa.x, ta.x, tid);
        accum(h, xa.y, pa.y, ta.y, tid);
        accum(h, xa.z, pa.z, ta.z, tid);
        accum(h, xa.w, pa.w, ta.w, tid);

        accum(h, xb.x, pb.x, tb.x, tid);
        accum(h, xb.y, pb.y, tb.y, tid);
        accum(h, xb.z, pb.z, tb.z, tid);
        accum(h, xb.w, pb.w, tb.w, tid);
    }
    __syncthreads();

    // Block reduce: 128 threads = 32 bins x 4 quarters of 32 entries.
    const int bin = tid >> 2;
    const int j   = tid & 3;
    const int bi  = bin * THREADS + j * 32;

    float vd = 0.0f, vc = 0.0f;
    #pragma unroll
    for (int k = 0; k < 32; k++) {
        int kk = (k + tid) & 31;
        float2 e = h[bi + kk];
        vd += e.x;
        vc += e.y;
    }

    vd += __shfl_down_sync(0xffffffffu, vd, 1);
    vc += __shfl_down_sync(0xffffffffu, vc, 1);
    vd += __shfl_down_sync(0xffffffffu, vd, 2);
    vc += __shfl_down_sync(0xffffffffu, vc, 2);

    if (j == 0) {
        int g = chan * NB + bin;
        atomicAdd(&g_sum_d[g], (double)vd);
        atomicAdd(&g_cnt [g], (double)vc);
    }
}

__global__ void final_kernel(float* __restrict__ out) {
    // PDL: this kernel's launch/setup overhead (~3us T_ovh) overlaps with
    // hist_kernel execution; only the wait below serializes on completion.
    cudaGridDependencySynchronize();

    int i = threadIdx.x;
    float d = 0.0f;
    if (i < NCH * NB) {
        float cnt = (float)g_cnt[i];
        float sdv = (float)g_sum_d[i];
        if (cnt > 0.0f) d = fabsf(sdv / cnt);
        g_sum_d[i] = 0.0;   // reset for next launch (graph determinism)
        g_cnt [i] = 0.0;
    }
    #pragma unroll
    for (int s = 16; s > 0; s >>= 1)
        d += __shfl_down_sync(0xffffffffu, d, s);

    __shared__ float wsum[4];
    if ((i & 31) == 0) wsum[i >> 5] = d;
    __syncthreads();
    if (i == 0) out[0] = (wsum[0] + wsum[1] + wsum[2] + wsum[3]) / 96.0f;
}

extern "C" void kernel_launch(void* const* d_in, const int* in_sizes, int n_in,
                              void* d_out, int out_size)
{
    const float4* pred = (const float4*)d_in[0];
    const float4* targ = (const float4*)d_in[1];
    const float4* x    = (const float4*)d_in[2];
    float* out = (float*)d_out;

    hist_kernel<<<NBLOCKS, THREADS>>>(pred, targ, x);

    cudaLaunchConfig_t cfg = {};
    cfg.gridDim  = dim3(1, 1, 1);
    cfg.blockDim = dim3(128, 1, 1);
    cfg.dynamicSmemBytes = 0;
    cfg.stream = 0;
    cudaLaunchAttribute attr[1];
    attr[0].id = cudaLaunchAttributeProgrammaticStreamSerialization;
    attr[0].val.programmaticStreamSerializationAllowed = 1;
    cfg.attrs = attr;
    cfg.numAttrs = 1;
    cudaLaunchKernelEx(&cfg, final_kernel, out);
}

// round 16
// speedup vs baseline: 1.3144x; 1.0615x over previous
#include <cuda_runtime.h>
#include <cstdint>

#define NB 32
#define NCH 3
#define THREADS 128
#define B_PER_CHUNK 32
#define CHUNK_F4   65536                   // float4 per (n,c) chunk
#define NCHUNKS    (16*3)                  // 48
#define NBLOCKS    (NCHUNKS * B_PER_CHUNK) // 1536
#define TILE_F4    256                     // 4KB per array per stage
#define TILE_BYTES (TILE_F4 * 16)
#define NTILES     8                       // region = 2048 f4 per array per block
#define REGION_F4  (TILE_F4 * NTILES)
#define NSTAGE     3

// smem layout (dynamic):
#define HIST_BYTES  (NB * THREADS * 8)             // 32768 (float2 hist)
#define STAGE_BYTES (3 * TILE_BYTES)               // 12288 (x,p,t tiles)
#define STAGE_OFF   HIST_BYTES
#define MBAR_OFF    (STAGE_OFF + NSTAGE * STAGE_BYTES)  // 69632
#define SMEM_TOTAL  (MBAR_OFF + 32)

// Global accumulators. Zero-initialized at module load; final_kernel resets
// them after reading, so every (graph-replayed) launch starts from zero.
__device__ double g_sum_d[NCH * NB];
__device__ double g_cnt [NCH * NB];

__device__ __forceinline__ void mbar_init(uint32_t a, uint32_t cnt) {
    asm volatile("mbarrier.init.shared.b64 [%0], %1;" :: "r"(a), "r"(cnt) : "memory");
}

__device__ __forceinline__ void mbar_wait(uint32_t mb, uint32_t ph) {
    asm volatile(
        "{\n\t.reg .pred P;\n"
        "W%=:\n\tmbarrier.try_wait.parity.acquire.cta.shared::cta.b64 P, [%0], %1, 0x989680;\n"
        "\t@P bra D%=;\n\tbra W%=;\n"
        "D%=:\n\t}"
        :: "r"(mb), "r"(ph) : "memory");
}

// One elected thread: expect 3*TILE_BYTES, then 3 bulk async copies g->smem.
__device__ __forceinline__ void issue_stage(uint32_t mb, uint32_t ds,
                                            const float4* gx, const float4* gp,
                                            const float4* gt)
{
    asm volatile("mbarrier.arrive.expect_tx.shared.b64 _, [%0], %1;"
                 :: "r"(mb), "r"(3u * TILE_BYTES) : "memory");
    asm volatile("cp.async.bulk.shared::cta.global.mbarrier::complete_tx::bytes [%0], [%1], %2, [%3];"
                 :: "r"(ds),          "l"(gx), "r"((uint32_t)TILE_BYTES), "r"(mb) : "memory");
    asm volatile("cp.async.bulk.shared::cta.global.mbarrier::complete_tx::bytes [%0], [%1], %2, [%3];"
                 :: "r"(ds + 4096u),  "l"(gp), "r"((uint32_t)TILE_BYTES), "r"(mb) : "memory");
    asm volatile("cp.async.bulk.shared::cta.global.mbarrier::complete_tx::bytes [%0], [%1], %2, [%3];"
                 :: "r"(ds + 8192u),  "l"(gt), "r"((uint32_t)TILE_BYTES), "r"(mb) : "memory");
}

__device__ __forceinline__ void accum(float2* h, float xc, float pc, float tc, int tid)
{
    int b = (int)(xc * 32.0f);        // inputs uniform [0,1)
    b = min(b, NB - 1);               // x slightly <1 can round x*32 up to 32.0
    float2* e = &h[b * THREADS + tid];
    float2 v = *e;                    // LDS.64, conflict-free (lane stride 8B)
    v.x += pc - tc;
    v.y += 1.0f;
    *e = v;                           // STS.64
}

__global__ __launch_bounds__(THREADS)
void hist_kernel(const float4* __restrict__ pred,
                 const float4* __restrict__ targ,
                 const float4* __restrict__ x)
{
    extern __shared__ char smem[];
    float2* h = (float2*)smem;
    const uint32_t smem_base = (uint32_t)__cvta_generic_to_shared(smem);
    const uint32_t mbar_base = smem_base + MBAR_OFF;

    const int tid = threadIdx.x;

    #pragma unroll
    for (int b = 0; b < NB; b++)
        h[b * THREADS + tid] = make_float2(0.0f, 0.0f);

    if (tid == 0) {
        #pragma unroll
        for (int s = 0; s < NSTAGE; s++)
            mbar_init(mbar_base + s * 8, 1);
        asm volatile("fence.proxy.async.shared::cta;" ::: "memory");
    }
    __syncthreads();

    const int chunk = blockIdx.x / B_PER_CHUNK;   // (n*3 + c)
    const int sub   = blockIdx.x % B_PER_CHUNK;
    const int chan  = chunk % NCH;
    const size_t base = (size_t)chunk * CHUNK_F4 + (size_t)sub * REGION_F4;

    const float4* gx = x    + base;
    const float4* gp = pred + base;
    const float4* gt = targ + base;

    // Prologue: fill the 3-deep pipeline.
    if (tid == 0) {
        #pragma unroll
        for (int s = 0; s < NSTAGE; s++)
            issue_stage(mbar_base + s * 8, smem_base + STAGE_OFF + s * STAGE_BYTES,
                        gx + s * TILE_F4, gp + s * TILE_F4, gt + s * TILE_F4);
    }

    // Consume NTILES tiles; refill stage as soon as the block finishes it.
    for (int k = 0; k < NTILES; k++) {
        const int buf = k % NSTAGE;
        const uint32_t ph = (uint32_t)((k / NSTAGE) & 1);
        const uint32_t mb = mbar_base + buf * 8;

        mbar_wait(mb, ph);

        const float4* bx = (const float4*)(smem + STAGE_OFF + buf * STAGE_BYTES);
        const float4* bp = (const float4*)(smem + STAGE_OFF + buf * STAGE_BYTES + 4096);
        const float4* bt = (const float4*)(smem + STAGE_OFF + buf * STAGE_BYTES + 8192);

        float4 xa = bx[tid];
        float4 pa = bp[tid];
        float4 ta = bt[tid];
        float4 xb = bx[tid + THREADS];
        float4 pb = bp[tid + THREADS];
        float4 tb = bt[tid + THREADS];

        accum(h, xa.x, pa.x, ta.x, tid);
        accum(h, xa.y, pa.y, ta.y, tid);
        accum(h, xa.z, pa.z, ta.z, tid);
        accum(h, xa.w, pa.w, ta.w, tid);
        accum(h, xb.x, pb.x, tb.x, tid);
        accum(h, xb.y, pb.y, tb.y, tid);
        accum(h, xb.z, pb.z, tb.z, tid);
        accum(h, xb.w, pb.w, tb.w, tid);

        __syncthreads();   // all warps done reading this stage

        if (tid == 0 && k + NSTAGE < NTILES)
            issue_stage(mb, smem_base + STAGE_OFF + buf * STAGE_BYTES,
                        gx + (k + NSTAGE) * TILE_F4,
                        gp + (k + NSTAGE) * TILE_F4,
                        gt + (k + NSTAGE) * TILE_F4);
    }

    // Block reduce: 128 threads = 32 bins x 4 quarters of 32 entries.
    const int bin = tid >> 2;
    const int j   = tid & 3;
    const int bi  = bin * THREADS + j * 32;

    float vd = 0.0f, vc = 0.0f;
    #pragma unroll
    for (int k = 0; k < 32; k++) {
        int kk = (k + tid) & 31;
        float2 e = h[bi + kk];
        vd += e.x;
        vc += e.y;
    }

    vd += __shfl_down_sync(0xffffffffu, vd, 1);
    vc += __shfl_down_sync(0xffffffffu, vc, 1);
    vd += __shfl_down_sync(0xffffffffu, vd, 2);
    vc += __shfl_down_sync(0xffffffffu, vc, 2);

    if (j == 0) {
        int g = chan * NB + bin;
        atomicAdd(&g_sum_d[g], (double)vd);
        atomicAdd(&g_cnt [g], (double)vc);
    }
}

__global__ void final_kernel(float* __restrict__ out) {
    // PDL: launch/setup overlaps hist_kernel; wait serializes on completion.
    cudaGridDependencySynchronize();

    int i = threadIdx.x;
    float d = 0.0f;
    if (i < NCH * NB) {
        float cnt = (float)g_cnt[i];
        float sdv = (float)g_sum_d[i];
        if (cnt > 0.0f) d = fabsf(sdv / cnt);
        g_sum_d[i] = 0.0;   // reset for next launch (graph determinism)
        g_cnt [i] = 0.0;
    }
    #pragma unroll
    for (int s = 16; s > 0; s >>= 1)
        d += __shfl_down_sync(0xffffffffu, d, s);

    __shared__ float wsum[4];
    if ((i & 31) == 0) wsum[i >> 5] = d;
    __syncthreads();
    if (i == 0) out[0] = (wsum[0] + wsum[1] + wsum[2] + wsum[3]) / 96.0f;
}

extern "C" void kernel_launch(void* const* d_in, const int* in_sizes, int n_in,
                              void* d_out, int out_size)
{
    const float4* pred = (const float4*)d_in[0];
    const float4* targ = (const float4*)d_in[1];
    const float4* x    = (const float4*)d_in[2];
    float* out = (float*)d_out;

    cudaFuncSetAttribute(hist_kernel,
                         cudaFuncAttributeMaxDynamicSharedMemorySize, SMEM_TOTAL);

    hist_kernel<<<NBLOCKS, THREADS, SMEM_TOTAL>>>(pred, targ, x);

    cudaLaunchConfig_t cfg = {};
    cfg.gridDim  = dim3(1, 1, 1);
    cfg.blockDim = dim3(128, 1, 1);
    cfg.dynamicSmemBytes = 0;
    cfg.stream = 0;
    cudaLaunchAttribute attr[1];
    attr[0].id = cudaLaunchAttributeProgrammaticStreamSerialization;
    attr[0].val.programmaticStreamSerializationAllowed = 1;
    cfg.attrs = attr;
    cfg.numAttrs = 1;
    cudaLaunchKernelEx(&cfg, final_kernel, out);
}